// round 11
// baseline (speedup 1.0000x reference)
#include <cuda_runtime.h>
#include <cstdint>

#define BB 2
#define CC 64
#define CQ 16
#define DD 96
#define PP 9216                    // H*W
#define PDSTRIDE (PP*DD)           // per-channel stride in x
#define CPD (CC*PDSTRIDE)          // per-batch stride in x
#define PCHUNK 32                  // p per block (energy), 2 per iteration
#define OPB 32                     // p per block (out), 2 per iteration

typedef unsigned long long u64;

__device__ double g_energy[BB*DD*DD];
__device__ int    g_nnz [BB*DD];
__device__ int    g_eidx[BB*DD*DD];
__device__ float  g_aval[BB*DD*DD];

// ---- packed f32x2 helpers (FFMA2 path only reachable via PTX) ----
__device__ __forceinline__ u64 pk2(float lo, float hi) {
    u64 r; asm("mov.b64 %0, {%1, %2};" : "=l"(r) : "f"(lo), "f"(hi)); return r;
}
__device__ __forceinline__ u64 bc2(float v) { return pk2(v, v); }
__device__ __forceinline__ void up2(float& lo, float& hi, u64 v) {
    asm("mov.b64 {%0, %1}, %2;" : "=f"(lo), "=f"(hi) : "l"(v));
}
__device__ __forceinline__ u64 ffma2(u64 a, u64 b, u64 c) {
    u64 d; asm("fma.rn.f32x2 %0, %1, %2, %3;" : "=l"(d) : "l"(a), "l"(b), "l"(c));
    return d;
}

// ===========================================================================
// Kernel A (R9 verbatim, measured 357us): 2 slabs/iter; QK warp-split
// (2 cq x 3 d-pairs per thread); accum over both slabs (R3 tile).
// ===========================================================================
#define WQS 68                          // padded weight stride (float4-clean)
#define E_WQ 0
#define E_WK (E_WQ + CQ*WQS)            // 1088
#define E_X  (E_WK + CQ*WQS)            // 2176
#define E_Q  (E_X + 2*CC*DD)            // 14464
#define E_K  (E_Q + 2*CQ*DD)            // 17536
#define E_FLOATS (E_K + 2*CQ*DD)        // 20608 floats = 82432 B

__global__ void __launch_bounds__(256, 2) energy_k(
    const float* __restrict__ x,
    const float* __restrict__ Wq, const float* __restrict__ bq,
    const float* __restrict__ Wk, const float* __restrict__ bk)
{
    extern __shared__ __align__(16) float esm[];
    float* sWq = esm + E_WQ;
    float* sWk = esm + E_WK;
    float* sX0 = esm + E_X;             // slab s at +s*CC*DD
    float* sQ0 = esm + E_Q;             // slab s at +s*CQ*DD
    float* sK0 = esm + E_K;

    const int t  = threadIdx.x;
    const int b  = blockIdx.y;
    const int p0 = blockIdx.x * PCHUNK;

    for (int i = t; i < CQ*CC; i += 256) {
        const int cq = i >> 6, c = i & 63;
        sWq[cq*WQS + c] = Wq[i];
        sWk[cq*WQS + c] = Wk[i];
    }

    const int sh  = t >> 7;             // slab half
    const int u   = (t >> 4) & 7;       // cq pair {2u, 2u+1}
    const int dxb = 6 * (t & 15);
    const float bq0 = bq[2*u], bq1 = bq[2*u+1];
    const float bk0 = bk[2*u], bk1 = bk[2*u+1];

    const int tx = t & 15;
    const int ty = t >> 4;

    u64 acc[6][3];
    #pragma unroll
    for (int i = 0; i < 6; ++i)
        #pragma unroll
        for (int j = 0; j < 3; ++j) acc[i][j] = 0ull;

    const float* xb = x + (size_t)b * CPD;

    float4 r4[12];
    #define LDG2(PBASE) {                                                       \
        _Pragma("unroll")                                                       \
        for (int rr = 0; rr < 12; ++rr) {                                       \
            const int idx = t + rr*256;                                         \
            const int s = (rr >= 6);                                            \
            const int j = idx - s*1536;                                         \
            const int c = j / 24, d4 = j - c*24;                                \
            r4[rr] = *reinterpret_cast<const float4*>(                          \
                xb + (size_t)c * PDSTRIDE + (size_t)((PBASE) + s) * DD + 4*d4); } }
    #define STS2() {                                                            \
        _Pragma("unroll")                                                       \
        for (int rr = 0; rr < 12; ++rr) {                                       \
            const int idx = t + rr*256;                                         \
            const int s = (rr >= 6);                                            \
            const int j = idx - s*1536;                                         \
            const int c = j / 24, d4 = j - c*24;                                \
            *reinterpret_cast<float4*>(&sX0[s*(CC*DD) + c*DD + 4*d4]) = r4[rr]; } }

    LDG2(p0);

    for (int it = 0; it < PCHUNK/2; ++it) {
        STS2();
        __syncthreads();

        // ---- QK for my slab: 2 cq x 3 d-pairs, weights via float4/4c ----
        {
            const float* sX = sX0 + sh*(CC*DD);
            u64 qa0[3], qa1[3], ka0[3], ka1[3];
            #pragma unroll
            for (int j = 0; j < 3; ++j) {
                qa0[j] = bc2(bq0); qa1[j] = bc2(bq1);
                ka0[j] = bc2(bk0); ka1[j] = bc2(bk1);
            }
            #pragma unroll 4
            for (int c4 = 0; c4 < CC; c4 += 4) {
                const float4 wq40 = *reinterpret_cast<const float4*>(&sWq[(2*u)*WQS + c4]);
                const float4 wq41 = *reinterpret_cast<const float4*>(&sWq[(2*u+1)*WQS + c4]);
                const float4 wk40 = *reinterpret_cast<const float4*>(&sWk[(2*u)*WQS + c4]);
                const float4 wk41 = *reinterpret_cast<const float4*>(&sWk[(2*u+1)*WQS + c4]);
                const float wq0a[4] = {wq40.x, wq40.y, wq40.z, wq40.w};
                const float wq1a[4] = {wq41.x, wq41.y, wq41.z, wq41.w};
                const float wk0a[4] = {wk40.x, wk40.y, wk40.z, wk40.w};
                const float wk1a[4] = {wk41.x, wk41.y, wk41.z, wk41.w};
                #pragma unroll
                for (int cc = 0; cc < 4; ++cc) {
                    const int c = c4 + cc;
                    u64 xv[3];
                    #pragma unroll
                    for (int j = 0; j < 3; ++j)
                        xv[j] = *reinterpret_cast<const u64*>(&sX[c*DD + dxb + 2*j]);
                    const u64 wqb0 = bc2(wq0a[cc]);
                    const u64 wqb1 = bc2(wq1a[cc]);
                    const u64 wkb0 = bc2(wk0a[cc]);
                    const u64 wkb1 = bc2(wk1a[cc]);
                    #pragma unroll
                    for (int j = 0; j < 3; ++j) {
                        qa0[j] = ffma2(wqb0, xv[j], qa0[j]);
                        qa1[j] = ffma2(wqb1, xv[j], qa1[j]);
                        ka0[j] = ffma2(wkb0, xv[j], ka0[j]);
                        ka1[j] = ffma2(wkb1, xv[j], ka1[j]);
                    }
                }
            }
            float* sQ = sQ0 + sh*(CQ*DD);
            float* sK = sK0 + sh*(CQ*DD);
            #pragma unroll
            for (int j = 0; j < 3; ++j) {
                *reinterpret_cast<u64*>(&sQ[(2*u)*DD   + dxb + 2*j]) = qa0[j];
                *reinterpret_cast<u64*>(&sQ[(2*u+1)*DD + dxb + 2*j]) = qa1[j];
                *reinterpret_cast<u64*>(&sK[(2*u)*DD   + dxb + 2*j]) = ka0[j];
                *reinterpret_cast<u64*>(&sK[(2*u+1)*DD + dxb + 2*j]) = ka1[j];
            }
        }

        if (it + 1 < PCHUNK/2) LDG2(p0 + 2*(it+1));   // overlap with accum
        __syncthreads();

        // ---- accum both slabs ----
        #pragma unroll
        for (int s = 0; s < 2; ++s) {
            const float* sQ = sQ0 + s*(CQ*DD);
            const float* sK = sK0 + s*(CQ*DD);
            #pragma unroll 2
            for (int cq = 0; cq < CQ; ++cq) {
                u64 kv[3];
                #pragma unroll
                for (int j = 0; j < 3; ++j)
                    kv[j] = *reinterpret_cast<const u64*>(&sK[cq*DD + 6*ty + 2*j]);
                #pragma unroll
                for (int i = 0; i < 6; ++i) {
                    const u64 qb = bc2(sQ[cq*DD + tx + 16*i]);
                    #pragma unroll
                    for (int j = 0; j < 3; ++j)
                        acc[i][j] = ffma2(qb, kv[j], acc[i][j]);
                }
            }
        }
        __syncthreads();
    }

    const size_t eb = (size_t)b * DD * DD;
    #pragma unroll
    for (int i = 0; i < 6; ++i)
        #pragma unroll
        for (int j = 0; j < 3; ++j) {
            float lo, hi;
            up2(lo, hi, acc[i][j]);
            const size_t base = eb + (size_t)(tx + 16*i)*DD + (6*ty + 2*j);
            atomicAdd(&g_energy[base],     (double)lo);
            atomicAdd(&g_energy[base + 1], (double)hi);
        }
    #undef LDG2
    #undef STS2
}

// ===========================================================================
// Kernel B: row softmax + compaction (a > 1e-8). One warp per (b,d) row.
// ===========================================================================
#define ATHRESH 1e-8f

__global__ void __launch_bounds__(128) softmax_k()
{
    const int w    = (blockIdx.x * blockDim.x + threadIdx.x) >> 5;
    const int lane = threadIdx.x & 31;
    if (w >= BB*DD) return;

    const double* er = g_energy + (size_t)w * DD;
    float v0 = (float)er[lane];
    float v1 = (float)er[lane + 32];
    float v2 = (float)er[lane + 64];

    float m = fmaxf(v0, fmaxf(v1, v2));
    #pragma unroll
    for (int o = 16; o > 0; o >>= 1) m = fmaxf(m, __shfl_xor_sync(0xffffffffu, m, o));

    float e0 = expf(v0 - m), e1 = expf(v1 - m), e2 = expf(v2 - m);
    float s = e0 + e1 + e2;
    #pragma unroll
    for (int o = 16; o > 0; o >>= 1) s += __shfl_xor_sync(0xffffffffu, s, o);

    const float inv = 1.0f / s;
    const float a[3] = { e0 * inv, e1 * inv, e2 * inv };

    int* ei = g_eidx + (size_t)w * DD;
    float* av = g_aval + (size_t)w * DD;
    const unsigned lmask = (1u << lane) - 1u;
    int base = 0;
    #pragma unroll
    for (int sct = 0; sct < 3; ++sct) {
        const bool keep = a[sct] > ATHRESH;
        const unsigned mask = __ballot_sync(0xffffffffu, keep);
        if (keep) {
            const int idx = base + __popc(mask & lmask);
            ei[idx] = lane + 32*sct;
            av[idx] = a[sct];
        }
        base += __popc(mask);
    }
    if (lane == 0) g_nnz[w] = base;
}

// ===========================================================================
// Kernel C v3: energy_k-style skeleton. 2 slabs per iteration, float4
// register prefetch, 3 barriers per 2p. V = Wv X + bv with float4 weight
// loads (broadcast) -> no up2 movs; 4c x 3 e-pair accum tile (no spills).
// Register-cached top-2 sparse gather (R7). SMEM 114688 B -> 2 CTAs/SM.
// ===========================================================================
#define S_WV 0
#define S_X  (S_WV + CC*CC)              // 4096 floats
#define S_V  (S_X + 2*CC*DD)             // 16384 floats
#define S_FLOATS (S_V + 2*CC*DD)         // 28672 floats = 114688 B

__global__ void __launch_bounds__(256, 2) outw_k(
    const float* __restrict__ x, const float* __restrict__ Wv,
    const float* __restrict__ bv, const float* __restrict__ gamma,
    float* __restrict__ out)
{
    extern __shared__ __align__(16) float osm[];
    float* sWv = osm + S_WV;             // [c_out][c2] stride 64
    float* sX0 = osm + S_X;              // slab s at +s*CC*DD
    float* sV0 = osm + S_V;              // slab s at +s*CC*DD, [c][e] stride 96

    const int t    = threadIdx.x;
    const int b    = blockIdx.y;
    const int p0   = blockIdx.x * OPB;
    const int tx   = t & 15;             // e-group: e = 6*tx + {0..5}
    const int ty   = t >> 4;             // c-group: c = 4*ty + {0..3}
    const int exb  = 6 * tx;
    const int lane = t & 31;
    const int wrp  = t >> 5;

    for (int i = t; i < CC*CC; i += 256) sWv[i] = Wv[i];

    // ---- register-cached top-2 attn entries per owned d-row (R7) ----
    int   nL[3], e0L[3], e1L[3];
    float a0L[3], a1L[3];
    #pragma unroll
    for (int dd = 0; dd < 3; ++dd) {
        const int d = lane + 32*dd;
        const int w = b*DD + d;
        const int n = g_nnz[w];
        nL[dd]  = n;
        e0L[dd] = g_eidx[(size_t)w*DD];
        a0L[dd] = g_aval[(size_t)w*DD];
        e1L[dd] = (n > 1) ? g_eidx[(size_t)w*DD + 1] : 0;
        a1L[dd] = (n > 1) ? g_aval[(size_t)w*DD + 1] : 0.f;
    }

    const float g = gamma[0];
    float bvv[4];
    #pragma unroll
    for (int k = 0; k < 4; ++k) bvv[k] = bv[4*ty + k];

    const float* xb = x   + (size_t)b * CPD;
    float*       ob = out + (size_t)b * CPD;

    float4 r4[12];
    #define LDG2(PBASE) {                                                       \
        _Pragma("unroll")                                                       \
        for (int rr = 0; rr < 12; ++rr) {                                       \
            const int idx = t + rr*256;                                         \
            const int s = (rr >= 6);                                            \
            const int j = idx - s*1536;                                         \
            const int c = j / 24, d4 = j - c*24;                                \
            r4[rr] = *reinterpret_cast<const float4*>(                          \
                xb + (size_t)c * PDSTRIDE + (size_t)((PBASE) + s) * DD + 4*d4); } }
    #define STS2() {                                                            \
        _Pragma("unroll")                                                       \
        for (int rr = 0; rr < 12; ++rr) {                                       \
            const int idx = t + rr*256;                                         \
            const int s = (rr >= 6);                                            \
            const int j = idx - s*1536;                                         \
            const int c = j / 24, d4 = j - c*24;                                \
            *reinterpret_cast<float4*>(&sX0[s*(CC*DD) + c*DD + 4*d4]) = r4[rr]; } }

    LDG2(p0);

    for (int it = 0; it < OPB/2; ++it) {
        STS2();
        __syncthreads();                 // (a) X both slabs visible

        // ---- V = Wv X + bv for both slabs (float4 weights, no up2) ----
        #pragma unroll
        for (int s = 0; s < 2; ++s) {
            const float* sX = sX0 + s*(CC*DD);
            float* sV = sV0 + s*(CC*DD);

            u64 vv[4][3];
            #pragma unroll
            for (int k = 0; k < 4; ++k)
                #pragma unroll
                for (int j = 0; j < 3; ++j) vv[k][j] = bc2(bvv[k]);

            #pragma unroll 2
            for (int c4 = 0; c4 < CC; c4 += 4) {
                float4 w4[4];
                #pragma unroll
                for (int k = 0; k < 4; ++k)
                    w4[k] = *reinterpret_cast<const float4*>(&sWv[(4*ty + k)*CC + c4]);
                const float wsc[4][4] = {
                    {w4[0].x, w4[0].y, w4[0].z, w4[0].w},
                    {w4[1].x, w4[1].y, w4[1].z, w4[1].w},
                    {w4[2].x, w4[2].y, w4[2].z, w4[2].w},
                    {w4[3].x, w4[3].y, w4[3].z, w4[3].w}};
                #pragma unroll
                for (int cc = 0; cc < 4; ++cc) {
                    const int c2 = c4 + cc;
                    u64 xv[3];
                    #pragma unroll
                    for (int j = 0; j < 3; ++j)
                        xv[j] = *reinterpret_cast<const u64*>(&sX[c2*DD + exb + 2*j]);
                    #pragma unroll
                    for (int k = 0; k < 4; ++k) {
                        const u64 wb = bc2(wsc[k][cc]);
                        #pragma unroll
                        for (int j = 0; j < 3; ++j)
                            vv[k][j] = ffma2(wb, xv[j], vv[k][j]);
                    }
                }
            }
            #pragma unroll
            for (int k = 0; k < 4; ++k)
                #pragma unroll
                for (int j = 0; j < 3; ++j)
                    *reinterpret_cast<u64*>(&sV[(4*ty + k)*DD + exb + 2*j]) = vv[k][j];
        }

        if (it + 1 < OPB/2) LDG2(p0 + 2*(it+1));   // overlap with gather
        __syncthreads();                 // (b) V both slabs visible

        // ---- sparse gather both slabs: lanes over d, warps over c ----
        #pragma unroll
        for (int s = 0; s < 2; ++s) {
            const float* sV = sV0 + s*(CC*DD);
            const float* sX = sX0 + s*(CC*DD);
            const int p = p0 + 2*it + s;
            #pragma unroll
            for (int ci = 0; ci < 8; ++ci) {
                const int c = wrp + 8*ci;
                const float* vrow = &sV[c*DD];
                const float* xrow = &sX[c*DD];
                float* orow = ob + (size_t)c * PDSTRIDE + (size_t)p * DD;
                #pragma unroll
                for (int dd = 0; dd < 3; ++dd) {
                    const int d = lane + 32*dd;
                    float acc = a0L[dd] * vrow[e0L[dd]];
                    if (nL[dd] > 1) acc = fmaf(a1L[dd], vrow[e1L[dd]], acc);
                    if (nL[dd] > 2) {            // rare exact tail from global
                        const size_t w = (size_t)(b*DD + d) * DD;
                        for (int k = 2; k < nL[dd]; ++k)
                            acc = fmaf(g_aval[w + k], vrow[g_eidx[w + k]], acc);
                    }
                    orow[d] = fmaf(g, acc, xrow[d]);
                }
            }
        }
        __syncthreads();                 // (c) gather done; sX/sV reusable
    }
    #undef LDG2
    #undef STS2
}

// ---------------------------------------------------------------------------
extern "C" void kernel_launch(void* const* d_in, const int* in_sizes, int n_in,
                              void* d_out, int out_size)
{
    const float* x  = (const float*)d_in[0];
    const float* Wq = (const float*)d_in[1];
    const float* bq = (const float*)d_in[2];
    const float* Wk = (const float*)d_in[3];
    const float* bk = (const float*)d_in[4];
    const float* Wv = (const float*)d_in[5];
    const float* bv = (const float*)d_in[6];
    const float* gm = (const float*)d_in[7];
    float* out = (float*)d_out;

    void* eptr = nullptr;
    cudaGetSymbolAddress(&eptr, g_energy);
    cudaMemsetAsync(eptr, 0, sizeof(double)*BB*DD*DD, 0);

    cudaFuncSetAttribute(energy_k, cudaFuncAttributeMaxDynamicSharedMemorySize,
                         E_FLOATS * (int)sizeof(float));
    energy_k<<<dim3(PP/PCHUNK, BB), 256, E_FLOATS*sizeof(float)>>>(x, Wq, bq, Wk, bk);

    softmax_k<<<(BB*DD*32 + 127)/128, 128>>>();

    cudaFuncSetAttribute(outw_k, cudaFuncAttributeMaxDynamicSharedMemorySize,
                         S_FLOATS * (int)sizeof(float));
    outw_k<<<dim3(PP/OPB, BB), 256, S_FLOATS*sizeof(float)>>>(x, Wv, bv, gm, out);
}

// round 12
// speedup vs baseline: 1.2484x; 1.2484x over previous
#include <cuda_runtime.h>
#include <cuda_bf16.h>
#include <cstdint>

#define BB 2
#define CC 64
#define CQ 16
#define DD 96
#define PP 9216                    // H*W
#define PDSTRIDE (PP*DD)           // per-channel stride in x
#define CPD (CC*PDSTRIDE)          // per-batch stride in x
#define PCHUNK 32                  // p per block (energy), 2 per iteration
#define OPB 16                     // p per block (out)

typedef unsigned long long u64;
typedef unsigned int u32;

__device__ double g_energy[BB*DD*DD];
__device__ int    g_nnz [BB*DD];
__device__ int    g_eidx[BB*DD*DD];
__device__ float  g_aval[BB*DD*DD];

// ---- packed f32x2 helpers (FFMA2 path only reachable via PTX) ----
__device__ __forceinline__ u64 pk2(float lo, float hi) {
    u64 r; asm("mov.b64 %0, {%1, %2};" : "=l"(r) : "f"(lo), "f"(hi)); return r;
}
__device__ __forceinline__ u64 bc2(float v) { return pk2(v, v); }
__device__ __forceinline__ void up2(float& lo, float& hi, u64 v) {
    asm("mov.b64 {%0, %1}, %2;" : "=f"(lo), "=f"(hi) : "l"(v));
}
__device__ __forceinline__ u64 ffma2(u64 a, u64 b, u64 c) {
    u64 d; asm("fma.rn.f32x2 %0, %1, %2, %3;" : "=l"(d) : "l"(a), "l"(b), "l"(c));
    return d;
}

// ---- mma.sync bf16 (sm_80+ baseline PTX; compiles for compute_103) ----
__device__ __forceinline__ void mma16816(float* d, const u32* a, u32 b0, u32 b1) {
    asm volatile(
        "mma.sync.aligned.m16n8k16.row.col.f32.bf16.bf16.f32 "
        "{%0,%1,%2,%3},{%4,%5,%6,%7},{%8,%9},{%0,%1,%2,%3};"
        : "+f"(d[0]), "+f"(d[1]), "+f"(d[2]), "+f"(d[3])
        : "r"(a[0]), "r"(a[1]), "r"(a[2]), "r"(a[3]), "r"(b0), "r"(b1));
}
__device__ __forceinline__ void splitbf(float v, __nv_bfloat16& h, __nv_bfloat16& l) {
    h = __float2bfloat16(v);
    l = __float2bfloat16(v - __bfloat162float(h));
}
__device__ __forceinline__ u32 pkbf(__nv_bfloat16 lo16, __nv_bfloat16 hi16) {
    return ((u32)__bfloat16_as_ushort(hi16) << 16) | (u32)__bfloat16_as_ushort(lo16);
}

// ===========================================================================
// Kernel A (R9 verbatim, measured 357us)
// ===========================================================================
#define WQS 68
#define E_WQ 0
#define E_WK (E_WQ + CQ*WQS)
#define E_X  (E_WK + CQ*WQS)
#define E_Q  (E_X + 2*CC*DD)
#define E_K  (E_Q + 2*CQ*DD)
#define E_FLOATS (E_K + 2*CQ*DD)

__global__ void __launch_bounds__(256, 2) energy_k(
    const float* __restrict__ x,
    const float* __restrict__ Wq, const float* __restrict__ bq,
    const float* __restrict__ Wk, const float* __restrict__ bk)
{
    extern __shared__ __align__(16) float esm[];
    float* sWq = esm + E_WQ;
    float* sWk = esm + E_WK;
    float* sX0 = esm + E_X;
    float* sQ0 = esm + E_Q;
    float* sK0 = esm + E_K;

    const int t  = threadIdx.x;
    const int b  = blockIdx.y;
    const int p0 = blockIdx.x * PCHUNK;

    for (int i = t; i < CQ*CC; i += 256) {
        const int cq = i >> 6, c = i & 63;
        sWq[cq*WQS + c] = Wq[i];
        sWk[cq*WQS + c] = Wk[i];
    }

    const int sh  = t >> 7;
    const int u   = (t >> 4) & 7;
    const int dxb = 6 * (t & 15);
    const float bq0 = bq[2*u], bq1 = bq[2*u+1];
    const float bk0 = bk[2*u], bk1 = bk[2*u+1];

    const int tx = t & 15;
    const int ty = t >> 4;

    u64 acc[6][3];
    #pragma unroll
    for (int i = 0; i < 6; ++i)
        #pragma unroll
        for (int j = 0; j < 3; ++j) acc[i][j] = 0ull;

    const float* xb = x + (size_t)b * CPD;

    float4 r4[12];
    #define LDG2(PBASE) {                                                       \
        _Pragma("unroll")                                                       \
        for (int rr = 0; rr < 12; ++rr) {                                       \
            const int idx = t + rr*256;                                         \
            const int s = (rr >= 6);                                            \
            const int j = idx - s*1536;                                         \
            const int c = j / 24, d4 = j - c*24;                                \
            r4[rr] = *reinterpret_cast<const float4*>(                          \
                xb + (size_t)c * PDSTRIDE + (size_t)((PBASE) + s) * DD + 4*d4); } }
    #define STS2() {                                                            \
        _Pragma("unroll")                                                       \
        for (int rr = 0; rr < 12; ++rr) {                                       \
            const int idx = t + rr*256;                                         \
            const int s = (rr >= 6);                                            \
            const int j = idx - s*1536;                                         \
            const int c = j / 24, d4 = j - c*24;                                \
            *reinterpret_cast<float4*>(&sX0[s*(CC*DD) + c*DD + 4*d4]) = r4[rr]; } }

    LDG2(p0);

    for (int it = 0; it < PCHUNK/2; ++it) {
        STS2();
        __syncthreads();

        {
            const float* sX = sX0 + sh*(CC*DD);
            u64 qa0[3], qa1[3], ka0[3], ka1[3];
            #pragma unroll
            for (int j = 0; j < 3; ++j) {
                qa0[j] = bc2(bq0); qa1[j] = bc2(bq1);
                ka0[j] = bc2(bk0); ka1[j] = bc2(bk1);
            }
            #pragma unroll 4
            for (int c4 = 0; c4 < CC; c4 += 4) {
                const float4 wq40 = *reinterpret_cast<const float4*>(&sWq[(2*u)*WQS + c4]);
                const float4 wq41 = *reinterpret_cast<const float4*>(&sWq[(2*u+1)*WQS + c4]);
                const float4 wk40 = *reinterpret_cast<const float4*>(&sWk[(2*u)*WQS + c4]);
                const float4 wk41 = *reinterpret_cast<const float4*>(&sWk[(2*u+1)*WQS + c4]);
                const float wq0a[4] = {wq40.x, wq40.y, wq40.z, wq40.w};
                const float wq1a[4] = {wq41.x, wq41.y, wq41.z, wq41.w};
                const float wk0a[4] = {wk40.x, wk40.y, wk40.z, wk40.w};
                const float wk1a[4] = {wk41.x, wk41.y, wk41.z, wk41.w};
                #pragma unroll
                for (int cc = 0; cc < 4; ++cc) {
                    const int c = c4 + cc;
                    u64 xv[3];
                    #pragma unroll
                    for (int j = 0; j < 3; ++j)
                        xv[j] = *reinterpret_cast<const u64*>(&sX[c*DD + dxb + 2*j]);
                    const u64 wqb0 = bc2(wq0a[cc]);
                    const u64 wqb1 = bc2(wq1a[cc]);
                    const u64 wkb0 = bc2(wk0a[cc]);
                    const u64 wkb1 = bc2(wk1a[cc]);
                    #pragma unroll
                    for (int j = 0; j < 3; ++j) {
                        qa0[j] = ffma2(wqb0, xv[j], qa0[j]);
                        qa1[j] = ffma2(wqb1, xv[j], qa1[j]);
                        ka0[j] = ffma2(wkb0, xv[j], ka0[j]);
                        ka1[j] = ffma2(wkb1, xv[j], ka1[j]);
                    }
                }
            }
            float* sQ = sQ0 + sh*(CQ*DD);
            float* sK = sK0 + sh*(CQ*DD);
            #pragma unroll
            for (int j = 0; j < 3; ++j) {
                *reinterpret_cast<u64*>(&sQ[(2*u)*DD   + dxb + 2*j]) = qa0[j];
                *reinterpret_cast<u64*>(&sQ[(2*u+1)*DD + dxb + 2*j]) = qa1[j];
                *reinterpret_cast<u64*>(&sK[(2*u)*DD   + dxb + 2*j]) = ka0[j];
                *reinterpret_cast<u64*>(&sK[(2*u+1)*DD + dxb + 2*j]) = ka1[j];
            }
        }

        if (it + 1 < PCHUNK/2) LDG2(p0 + 2*(it+1));
        __syncthreads();

        #pragma unroll
        for (int s = 0; s < 2; ++s) {
            const float* sQ = sQ0 + s*(CQ*DD);
            const float* sK = sK0 + s*(CQ*DD);
            #pragma unroll 2
            for (int cq = 0; cq < CQ; ++cq) {
                u64 kv[3];
                #pragma unroll
                for (int j = 0; j < 3; ++j)
                    kv[j] = *reinterpret_cast<const u64*>(&sK[cq*DD + 6*ty + 2*j]);
                #pragma unroll
                for (int i = 0; i < 6; ++i) {
                    const u64 qb = bc2(sQ[cq*DD + tx + 16*i]);
                    #pragma unroll
                    for (int j = 0; j < 3; ++j)
                        acc[i][j] = ffma2(qb, kv[j], acc[i][j]);
                }
            }
        }
        __syncthreads();
    }

    const size_t eb = (size_t)b * DD * DD;
    #pragma unroll
    for (int i = 0; i < 6; ++i)
        #pragma unroll
        for (int j = 0; j < 3; ++j) {
            float lo, hi;
            up2(lo, hi, acc[i][j]);
            const size_t base = eb + (size_t)(tx + 16*i)*DD + (6*ty + 2*j);
            atomicAdd(&g_energy[base],     (double)lo);
            atomicAdd(&g_energy[base + 1], (double)hi);
        }
    #undef LDG2
    #undef STS2
}

// ===========================================================================
// Kernel B: row softmax + compaction (a > 1e-8). One warp per (b,d) row.
// ===========================================================================
#define ATHRESH 1e-8f

__global__ void __launch_bounds__(128) softmax_k()
{
    const int w    = (blockIdx.x * blockDim.x + threadIdx.x) >> 5;
    const int lane = threadIdx.x & 31;
    if (w >= BB*DD) return;

    const double* er = g_energy + (size_t)w * DD;
    float v0 = (float)er[lane];
    float v1 = (float)er[lane + 32];
    float v2 = (float)er[lane + 64];

    float m = fmaxf(v0, fmaxf(v1, v2));
    #pragma unroll
    for (int o = 16; o > 0; o >>= 1) m = fmaxf(m, __shfl_xor_sync(0xffffffffu, m, o));

    float e0 = expf(v0 - m), e1 = expf(v1 - m), e2 = expf(v2 - m);
    float s = e0 + e1 + e2;
    #pragma unroll
    for (int o = 16; o > 0; o >>= 1) s += __shfl_xor_sync(0xffffffffu, s, o);

    const float inv = 1.0f / s;
    const float a[3] = { e0 * inv, e1 * inv, e2 * inv };

    int* ei = g_eidx + (size_t)w * DD;
    float* av = g_aval + (size_t)w * DD;
    const unsigned lmask = (1u << lane) - 1u;
    int base = 0;
    #pragma unroll
    for (int sct = 0; sct < 3; ++sct) {
        const bool keep = a[sct] > ATHRESH;
        const unsigned mask = __ballot_sync(0xffffffffu, keep);
        if (keep) {
            const int idx = base + __popc(mask & lmask);
            ei[idx] = lane + 32*sct;
            av[idx] = a[sct];
        }
        base += __popc(mask);
    }
    if (lane == 0) g_nnz[w] = base;
}

// ===========================================================================
// Kernel C v4 (tensor): V^T-GEMM via mma.sync bf16 split-3.
//   V[c,e] = sum_c2 Wv[c,c2] X[c2,e] + bv[c]  per p
//   A = Wv (regs, bf16 hi/lo frags, built once), B = X (fused bf16 conversion
//   into [e][c2-pair] packed words, stride 37), D fp32 accum init = bias.
// Then R10's register-cached sparse gather + residual.
// ===========================================================================
#define XBW 37                           // word stride of packed bf16 X tiles
#define SVS 100                          // sV float stride
#define F_SX  0                          // 64 x 96 fp32
#define F_SV  (F_SX + CC*DD)             // 64 x 100 fp32 -> 12544
#define W_BH  (F_SV + CC*SVS)            // words: 96 x 37
#define W_BL  (W_BH + DD*XBW)
#define O_FLOATS (W_BL + DD*XBW)         // 19648 floats = 78592 B

__global__ void __launch_bounds__(256, 2) outm_k(
    const float* __restrict__ x, const float* __restrict__ Wv,
    const float* __restrict__ bv, const float* __restrict__ gamma,
    float* __restrict__ out)
{
    extern __shared__ __align__(16) float osm[];
    float* sX  = osm + F_SX;
    float* sV  = osm + F_SV;
    u32*   sBh = (u32*)(osm + W_BH);
    u32*   sBl = (u32*)(osm + W_BL);

    const int t    = threadIdx.x;
    const int b    = blockIdx.y;
    const int p0   = blockIdx.x * OPB;
    const int lane = t & 31;
    const int wrp  = t >> 5;
    const int lg   = lane >> 2;          // 0..7
    const int tc   = lane & 3;           // 0..3
    const int mt   = wrp >> 1;           // m-tile 0..3 (c rows mt*16..+15)
    const int nb   = (wrp & 1) * 48;     // e strip base

    // ---- A = Wv bf16 hi/lo fragments in registers (built once) ----
    u32 ah[4][4], al[4][4];
    {
        const int r0 = mt*16 + lg, r1 = r0 + 8;
        #pragma unroll
        for (int kt = 0; kt < 4; ++kt) {
            const int c0 = kt*16 + 2*tc;
            const float w00 = Wv[r0*CC + c0],     w01 = Wv[r0*CC + c0 + 1];
            const float w10 = Wv[r1*CC + c0],     w11 = Wv[r1*CC + c0 + 1];
            const float w02 = Wv[r0*CC + c0 + 8], w03 = Wv[r0*CC + c0 + 9];
            const float w12 = Wv[r1*CC + c0 + 8], w13 = Wv[r1*CC + c0 + 9];
            __nv_bfloat16 h, l, h2, l2;
            splitbf(w00, h, l); splitbf(w01, h2, l2);
            ah[kt][0] = pkbf(h, h2); al[kt][0] = pkbf(l, l2);
            splitbf(w10, h, l); splitbf(w11, h2, l2);
            ah[kt][1] = pkbf(h, h2); al[kt][1] = pkbf(l, l2);
            splitbf(w02, h, l); splitbf(w03, h2, l2);
            ah[kt][2] = pkbf(h, h2); al[kt][2] = pkbf(l, l2);
            splitbf(w12, h, l); splitbf(w13, h2, l2);
            ah[kt][3] = pkbf(h, h2); al[kt][3] = pkbf(l, l2);
        }
    }
    const float bA = bv[mt*16 + lg];
    const float bB = bv[mt*16 + lg + 8];

    // ---- register-cached top-2 attn entries per owned d-row (R7) ----
    int   nL[3], e0L[3], e1L[3];
    float a0L[3], a1L[3];
    #pragma unroll
    for (int dd = 0; dd < 3; ++dd) {
        const int d = lane + 32*dd;
        const int w = b*DD + d;
        const int n = g_nnz[w];
        nL[dd]  = n;
        e0L[dd] = g_eidx[(size_t)w*DD];
        a0L[dd] = g_aval[(size_t)w*DD];
        e1L[dd] = (n > 1) ? g_eidx[(size_t)w*DD + 1] : 0;
        a1L[dd] = (n > 1) ? g_aval[(size_t)w*DD + 1] : 0.f;
    }
    const float gam = gamma[0];

    const float* xb = x   + (size_t)b * CPD;
    float*       ob = out + (size_t)b * CPD;

    // slab loader mapping: channel pair i, e-block j0..j0+11
    const int li = t >> 3;               // 0..31
    const int j0 = (t & 7) * 12;

    float4 r4[6];
    #define LDG1(P) {                                                           \
        const float* s0 = xb + (size_t)(2*li)   * PDSTRIDE + (size_t)(P) * DD + j0; \
        const float* s1 = xb + (size_t)(2*li+1) * PDSTRIDE + (size_t)(P) * DD + j0; \
        _Pragma("unroll")                                                       \
        for (int q = 0; q < 3; ++q) {                                           \
            r4[q]   = *reinterpret_cast<const float4*>(s0 + 4*q);               \
            r4[3+q] = *reinterpret_cast<const float4*>(s1 + 4*q); } }

    LDG1(p0);

    for (int pp = 0; pp < OPB; ++pp) {
        const int p = p0 + pp;

        // ---- store fp32 slab + fused bf16 split conversion ----
        {
            #pragma unroll
            for (int q = 0; q < 3; ++q) {
                *reinterpret_cast<float4*>(&sX[(2*li)*DD   + j0 + 4*q]) = r4[q];
                *reinterpret_cast<float4*>(&sX[(2*li+1)*DD + j0 + 4*q]) = r4[3+q];
            }
            const float* fr = reinterpret_cast<const float*>(r4);
            #pragma unroll
            for (int k = 0; k < 12; ++k) {
                const float v0 = fr[k], v1 = fr[12 + k];
                __nv_bfloat16 h0, l0, h1, l1;
                splitbf(v0, h0, l0);
                splitbf(v1, h1, l1);
                const int e = j0 + k;
                sBh[e*XBW + li] = pkbf(h0, h1);   // low = c2 even
                sBl[e*XBW + li] = pkbf(l0, l1);
            }
        }
        __syncthreads();                 // (a) slab + bf16 tiles visible

        if (pp + 1 < OPB) LDG1(p + 1);   // prefetch next slab

        // ---- mma: D(6 n-tiles x 4 regs) = split-3 bf16 GEMM + bias ----
        {
            float dacc[6][4];
            #pragma unroll
            for (int nt = 0; nt < 6; ++nt) {
                dacc[nt][0] = bA; dacc[nt][1] = bA;
                dacc[nt][2] = bB; dacc[nt][3] = bB;
            }
            #pragma unroll
            for (int nt = 0; nt < 6; ++nt) {
                const int eb = nb + nt*8 + lg;
                #pragma unroll
                for (int kt = 0; kt < 4; ++kt) {
                    const int wof = eb*XBW + kt*8 + tc;
                    const u32 b0h = sBh[wof], b1h = sBh[wof + 4];
                    const u32 b0l = sBl[wof], b1l = sBl[wof + 4];
                    mma16816(dacc[nt], ah[kt], b0h, b1h);
                    mma16816(dacc[nt], al[kt], b0h, b1h);
                    mma16816(dacc[nt], ah[kt], b0l, b1l);
                }
            }
            // epilogue: D -> sV[c][e]
            const int r0 = mt*16 + lg, r1 = r0 + 8;
            #pragma unroll
            for (int nt = 0; nt < 6; ++nt) {
                const int ec = nb + nt*8 + 2*tc;
                float2 v01; v01.x = dacc[nt][0]; v01.y = dacc[nt][1];
                float2 v23; v23.x = dacc[nt][2]; v23.y = dacc[nt][3];
                *reinterpret_cast<float2*>(&sV[r0*SVS + ec]) = v01;
                *reinterpret_cast<float2*>(&sV[r1*SVS + ec]) = v23;
            }
        }
        __syncthreads();                 // (b) V visible

        // ---- sparse gather + residual, coalesced STG ----
        #pragma unroll
        for (int ci = 0; ci < 8; ++ci) {
            const int c = wrp + 8*ci;
            const float* vrow = &sV[c*SVS];
            const float* xrow = &sX[c*DD];
            float* orow = ob + (size_t)c * PDSTRIDE + (size_t)p * DD;
            #pragma unroll
            for (int dd = 0; dd < 3; ++dd) {
                const int d = lane + 32*dd;
                float acc = a0L[dd] * vrow[e0L[dd]];
                if (nL[dd] > 1) acc = fmaf(a1L[dd], vrow[e1L[dd]], acc);
                if (nL[dd] > 2) {        // rare exact tail from global
                    const size_t w = (size_t)(b*DD + d) * DD;
                    for (int k = 2; k < nL[dd]; ++k)
                        acc = fmaf(g_aval[w + k], vrow[g_eidx[w + k]], acc);
                }
                orow[d] = fmaf(gam, acc, xrow[d]);
            }
        }
        __syncthreads();                 // (c) gather done; smem reusable
    }
    #undef LDG1
}

// ---------------------------------------------------------------------------
extern "C" void kernel_launch(void* const* d_in, const int* in_sizes, int n_in,
                              void* d_out, int out_size)
{
    const float* x  = (const float*)d_in[0];
    const float* Wq = (const float*)d_in[1];
    const float* bq = (const float*)d_in[2];
    const float* Wk = (const float*)d_in[3];
    const float* bk = (const float*)d_in[4];
    const float* Wv = (const float*)d_in[5];
    const float* bv = (const float*)d_in[6];
    const float* gm = (const float*)d_in[7];
    float* out = (float*)d_out;

    void* eptr = nullptr;
    cudaGetSymbolAddress(&eptr, g_energy);
    cudaMemsetAsync(eptr, 0, sizeof(double)*BB*DD*DD, 0);

    cudaFuncSetAttribute(energy_k, cudaFuncAttributeMaxDynamicSharedMemorySize,
                         E_FLOATS * (int)sizeof(float));
    energy_k<<<dim3(PP/PCHUNK, BB), 256, E_FLOATS*sizeof(float)>>>(x, Wq, bq, Wk, bk);

    softmax_k<<<(BB*DD*32 + 127)/128, 128>>>();

    cudaFuncSetAttribute(outm_k, cudaFuncAttributeMaxDynamicSharedMemorySize,
                         O_FLOATS * (int)sizeof(float));
    outm_k<<<dim3(PP/OPB, BB), 256, O_FLOATS*sizeof(float)>>>(x, Wv, bv, gm, out);
}

// round 14
// speedup vs baseline: 1.3254x; 1.0616x over previous
#include <cuda_runtime.h>
#include <cuda_bf16.h>
#include <cstdint>

#define BB 2
#define CC 64
#define CQ 16
#define DD 96
#define PP 9216                    // H*W
#define PDSTRIDE (PP*DD)           // per-channel stride in x
#define CPD (CC*PDSTRIDE)          // per-batch stride in x
#define PCHUNK 64                  // p per block (energy), 2 per iteration
#define OPB 32                     // p per block (out)

typedef unsigned long long u64;
typedef unsigned int u32;

__device__ double g_energy[BB*DD*DD];
__device__ int    g_nnz [BB*DD];
__device__ int    g_eidx[BB*DD*DD];
__device__ float  g_aval[BB*DD*DD];

// ---- packed f32x2 helpers ----
__device__ __forceinline__ u64 pk2(float lo, float hi) {
    u64 r; asm("mov.b64 %0, {%1, %2};" : "=l"(r) : "f"(lo), "f"(hi)); return r;
}
__device__ __forceinline__ u64 bc2(float v) { return pk2(v, v); }
__device__ __forceinline__ void up2(float& lo, float& hi, u64 v) {
    asm("mov.b64 {%0, %1}, %2;" : "=f"(lo), "=f"(hi) : "l"(v));
}
__device__ __forceinline__ u64 ffma2(u64 a, u64 b, u64 c) {
    u64 d; asm("fma.rn.f32x2 %0, %1, %2, %3;" : "=l"(d) : "l"(a), "l"(b), "l"(c));
    return d;
}

// ---- mma.sync bf16 ----
__device__ __forceinline__ void mma16816(float* d, const u32* a, u32 b0, u32 b1) {
    asm volatile(
        "mma.sync.aligned.m16n8k16.row.col.f32.bf16.bf16.f32 "
        "{%0,%1,%2,%3},{%4,%5,%6,%7},{%8,%9},{%0,%1,%2,%3};"
        : "+f"(d[0]), "+f"(d[1]), "+f"(d[2]), "+f"(d[3])
        : "r"(a[0]), "r"(a[1]), "r"(a[2]), "r"(a[3]), "r"(b0), "r"(b1));
}
__device__ __forceinline__ void splitbf(float v, __nv_bfloat16& h, __nv_bfloat16& l) {
    h = __float2bfloat16(v);
    l = __float2bfloat16(v - __bfloat162float(h));
}
__device__ __forceinline__ u32 pkbf(__nv_bfloat16 lo16, __nv_bfloat16 hi16) {
    return ((u32)__bfloat16_as_ushort(hi16) << 16) | (u32)__bfloat16_as_ushort(lo16);
}

// ===========================================================================
// Kernel A (R9 math verbatim; PCHUNK 64 -> single wave at occ 2)
// ===========================================================================
#define WQS 68
#define E_WQ 0
#define E_WK (E_WQ + CQ*WQS)
#define E_X  (E_WK + CQ*WQS)
#define E_Q  (E_X + 2*CC*DD)
#define E_K  (E_Q + 2*CQ*DD)
#define E_FLOATS (E_K + 2*CQ*DD)

__global__ void __launch_bounds__(256, 2) energy_k(
    const float* __restrict__ x,
    const float* __restrict__ Wq, const float* __restrict__ bq,
    const float* __restrict__ Wk, const float* __restrict__ bk)
{
    extern __shared__ __align__(16) float esm[];
    float* sWq = esm + E_WQ;
    float* sWk = esm + E_WK;
    float* sX0 = esm + E_X;
    float* sQ0 = esm + E_Q;
    float* sK0 = esm + E_K;

    const int t  = threadIdx.x;
    const int b  = blockIdx.y;
    const int p0 = blockIdx.x * PCHUNK;

    for (int i = t; i < CQ*CC; i += 256) {
        const int cq = i >> 6, c = i & 63;
        sWq[cq*WQS + c] = Wq[i];
        sWk[cq*WQS + c] = Wk[i];
    }

    const int sh  = t >> 7;
    const int u   = (t >> 4) & 7;
    const int dxb = 6 * (t & 15);
    const float bq0 = bq[2*u], bq1 = bq[2*u+1];
    const float bk0 = bk[2*u], bk1 = bk[2*u+1];

    const int tx = t & 15;
    const int ty = t >> 4;

    u64 acc[6][3];
    #pragma unroll
    for (int i = 0; i < 6; ++i)
        #pragma unroll
        for (int j = 0; j < 3; ++j) acc[i][j] = 0ull;

    const float* xb = x + (size_t)b * CPD;

    float4 r4[12];
    #define LDG2(PBASE) {                                                       \
        _Pragma("unroll")                                                       \
        for (int rr = 0; rr < 12; ++rr) {                                       \
            const int idx = t + rr*256;                                         \
            const int s = (rr >= 6);                                            \
            const int j = idx - s*1536;                                         \
            const int c = j / 24, d4 = j - c*24;                                \
            r4[rr] = *reinterpret_cast<const float4*>(                          \
                xb + (size_t)c * PDSTRIDE + (size_t)((PBASE) + s) * DD + 4*d4); } }
    #define STS2() {                                                            \
        _Pragma("unroll")                                                       \
        for (int rr = 0; rr < 12; ++rr) {                                       \
            const int idx = t + rr*256;                                         \
            const int s = (rr >= 6);                                            \
            const int j = idx - s*1536;                                         \
            const int c = j / 24, d4 = j - c*24;                                \
            *reinterpret_cast<float4*>(&sX0[s*(CC*DD) + c*DD + 4*d4]) = r4[rr]; } }

    LDG2(p0);

    for (int it = 0; it < PCHUNK/2; ++it) {
        STS2();
        __syncthreads();

        {
            const float* sX = sX0 + sh*(CC*DD);
            u64 qa0[3], qa1[3], ka0[3], ka1[3];
            #pragma unroll
            for (int j = 0; j < 3; ++j) {
                qa0[j] = bc2(bq0); qa1[j] = bc2(bq1);
                ka0[j] = bc2(bk0); ka1[j] = bc2(bk1);
            }
            #pragma unroll 4
            for (int c4 = 0; c4 < CC; c4 += 4) {
                const float4 wq40 = *reinterpret_cast<const float4*>(&sWq[(2*u)*WQS + c4]);
                const float4 wq41 = *reinterpret_cast<const float4*>(&sWq[(2*u+1)*WQS + c4]);
                const float4 wk40 = *reinterpret_cast<const float4*>(&sWk[(2*u)*WQS + c4]);
                const float4 wk41 = *reinterpret_cast<const float4*>(&sWk[(2*u+1)*WQS + c4]);
                const float wq0a[4] = {wq40.x, wq40.y, wq40.z, wq40.w};
                const float wq1a[4] = {wq41.x, wq41.y, wq41.z, wq41.w};
                const float wk0a[4] = {wk40.x, wk40.y, wk40.z, wk40.w};
                const float wk1a[4] = {wk41.x, wk41.y, wk41.z, wk41.w};
                #pragma unroll
                for (int cc = 0; cc < 4; ++cc) {
                    const int c = c4 + cc;
                    u64 xv[3];
                    #pragma unroll
                    for (int j = 0; j < 3; ++j)
                        xv[j] = *reinterpret_cast<const u64*>(&sX[c*DD + dxb + 2*j]);
                    const u64 wqb0 = bc2(wq0a[cc]);
                    const u64 wqb1 = bc2(wq1a[cc]);
                    const u64 wkb0 = bc2(wk0a[cc]);
                    const u64 wkb1 = bc2(wk1a[cc]);
                    #pragma unroll
                    for (int j = 0; j < 3; ++j) {
                        qa0[j] = ffma2(wqb0, xv[j], qa0[j]);
                        qa1[j] = ffma2(wqb1, xv[j], qa1[j]);
                        ka0[j] = ffma2(wkb0, xv[j], ka0[j]);
                        ka1[j] = ffma2(wkb1, xv[j], ka1[j]);
                    }
                }
            }
            float* sQ = sQ0 + sh*(CQ*DD);
            float* sK = sK0 + sh*(CQ*DD);
            #pragma unroll
            for (int j = 0; j < 3; ++j) {
                *reinterpret_cast<u64*>(&sQ[(2*u)*DD   + dxb + 2*j]) = qa0[j];
                *reinterpret_cast<u64*>(&sQ[(2*u+1)*DD + dxb + 2*j]) = qa1[j];
                *reinterpret_cast<u64*>(&sK[(2*u)*DD   + dxb + 2*j]) = ka0[j];
                *reinterpret_cast<u64*>(&sK[(2*u+1)*DD + dxb + 2*j]) = ka1[j];
            }
        }

        if (it + 1 < PCHUNK/2) LDG2(p0 + 2*(it+1));
        __syncthreads();

        #pragma unroll
        for (int s = 0; s < 2; ++s) {
            const float* sQ = sQ0 + s*(CQ*DD);
            const float* sK = sK0 + s*(CQ*DD);
            #pragma unroll 2
            for (int cq = 0; cq < CQ; ++cq) {
                u64 kv[3];
                #pragma unroll
                for (int j = 0; j < 3; ++j)
                    kv[j] = *reinterpret_cast<const u64*>(&sK[cq*DD + 6*ty + 2*j]);
                #pragma unroll
                for (int i = 0; i < 6; ++i) {
                    const u64 qb = bc2(sQ[cq*DD + tx + 16*i]);
                    #pragma unroll
                    for (int j = 0; j < 3; ++j)
                        acc[i][j] = ffma2(qb, kv[j], acc[i][j]);
                }
            }
        }
        __syncthreads();
    }

    const size_t eb = (size_t)b * DD * DD;
    #pragma unroll
    for (int i = 0; i < 6; ++i)
        #pragma unroll
        for (int j = 0; j < 3; ++j) {
            float lo, hi;
            up2(lo, hi, acc[i][j]);
            const size_t base = eb + (size_t)(tx + 16*i)*DD + (6*ty + 2*j);
            atomicAdd(&g_energy[base],     (double)lo);
            atomicAdd(&g_energy[base + 1], (double)hi);
        }
    #undef LDG2
    #undef STS2
}

// ===========================================================================
// Kernel B: row softmax + compaction (a > 1e-8). One warp per (b,d) row.
// ===========================================================================
#define ATHRESH 1e-8f

__global__ void __launch_bounds__(128) softmax_k()
{
    const int w    = (blockIdx.x * blockDim.x + threadIdx.x) >> 5;
    const int lane = threadIdx.x & 31;
    if (w >= BB*DD) return;

    const double* er = g_energy + (size_t)w * DD;
    float v0 = (float)er[lane];
    float v1 = (float)er[lane + 32];
    float v2 = (float)er[lane + 64];

    float m = fmaxf(v0, fmaxf(v1, v2));
    #pragma unroll
    for (int o = 16; o > 0; o >>= 1) m = fmaxf(m, __shfl_xor_sync(0xffffffffu, m, o));

    float e0 = expf(v0 - m), e1 = expf(v1 - m), e2 = expf(v2 - m);
    float s = e0 + e1 + e2;
    #pragma unroll
    for (int o = 16; o > 0; o >>= 1) s += __shfl_xor_sync(0xffffffffu, s, o);

    const float inv = 1.0f / s;
    const float a[3] = { e0 * inv, e1 * inv, e2 * inv };

    int* ei = g_eidx + (size_t)w * DD;
    float* av = g_aval + (size_t)w * DD;
    const unsigned lmask = (1u << lane) - 1u;
    int base = 0;
    #pragma unroll
    for (int sct = 0; sct < 3; ++sct) {
        const bool keep = a[sct] > ATHRESH;
        const unsigned mask = __ballot_sync(0xffffffffu, keep);
        if (keep) {
            const int idx = base + __popc(mask & lmask);
            ei[idx] = lane + 32*sct;
            av[idx] = a[sct];
        }
        base += __popc(mask);
    }
    if (lane == 0) g_nnz[w] = base;
}

// ===========================================================================
// Kernel C v5 (gather-before-GEMM): y[c2,d] = gamma*(a0 x[c2,e0] + a1 x[c2,e1]
//   + tail); out[c,p,d] = (Wv y)[c,d] + gamma*bv[c] + x[c,p,d].
// A = Wv bf16 hi/lo frags in regs; B = y split-bf16 [d][c2-pair] (XBW=37);
// D-fragments write straight to global with residual. 2 barriers/p.
// ===========================================================================
#define XBW 37
#define SXS 100
#define Y_SX 0                           // 2 x 64x100 fp32 (double buffer)
#define Y_BH (Y_SX + 2*CC*SXS)           // 12800
#define Y_BL (Y_BH + DD*XBW)             // +3552
#define Y_FLOATS (Y_BL + DD*XBW)         // 19904 floats = 79616 B

__global__ void __launch_bounds__(256, 2) outy_k(
    const float* __restrict__ x, const float* __restrict__ Wv,
    const float* __restrict__ bv, const float* __restrict__ gamma,
    float* __restrict__ out)
{
    extern __shared__ __align__(16) float osm[];
    float* sX0 = osm + Y_SX;
    u32*   sBh = (u32*)(osm + Y_BH);
    u32*   sBl = (u32*)(osm + Y_BL);

    const int t    = threadIdx.x;
    const int b    = blockIdx.y;
    const int p0   = blockIdx.x * OPB;
    const int lane = t & 31;
    const int wrp  = t >> 5;
    const int lg   = lane >> 2;
    const int tc   = lane & 3;
    const int mt   = wrp >> 1;           // c rows mt*16..+15
    const int nb   = (wrp & 1) * 48;     // d strip base

    const float gam = gamma[0];

    // ---- A = Wv bf16 hi/lo fragments (built once) ----
    u32 ah[4][4], al[4][4];
    {
        const int r0 = mt*16 + lg, r1 = r0 + 8;
        #pragma unroll
        for (int kt = 0; kt < 4; ++kt) {
            const int c0 = kt*16 + 2*tc;
            const float w00 = Wv[r0*CC + c0],     w01 = Wv[r0*CC + c0 + 1];
            const float w10 = Wv[r1*CC + c0],     w11 = Wv[r1*CC + c0 + 1];
            const float w02 = Wv[r0*CC + c0 + 8], w03 = Wv[r0*CC + c0 + 9];
            const float w12 = Wv[r1*CC + c0 + 8], w13 = Wv[r1*CC + c0 + 9];
            __nv_bfloat16 h, l, h2, l2;
            splitbf(w00, h, l); splitbf(w01, h2, l2);
            ah[kt][0] = pkbf(h, h2); al[kt][0] = pkbf(l, l2);
            splitbf(w10, h, l); splitbf(w11, h2, l2);
            ah[kt][1] = pkbf(h, h2); al[kt][1] = pkbf(l, l2);
            splitbf(w02, h, l); splitbf(w03, h2, l2);
            ah[kt][2] = pkbf(h, h2); al[kt][2] = pkbf(l, l2);
            splitbf(w12, h, l); splitbf(w13, h2, l2);
            ah[kt][3] = pkbf(h, h2); al[kt][3] = pkbf(l, l2);
        }
    }
    const float gbA = gam * bv[mt*16 + lg];
    const float gbB = gam * bv[mt*16 + lg + 8];

    // ---- attn cache (lane owns d = lane + 32*dd), pre-scaled by gamma ----
    int   nL[3], e0L[3], e1L[3];
    float ga0L[3], ga1L[3];
    #pragma unroll
    for (int dd = 0; dd < 3; ++dd) {
        const int d = lane + 32*dd;
        const int w = b*DD + d;
        const int n = g_nnz[w];
        nL[dd]  = n;
        e0L[dd] = g_eidx[(size_t)w*DD];
        ga0L[dd] = gam * g_aval[(size_t)w*DD];
        e1L[dd] = (n > 1) ? g_eidx[(size_t)w*DD + 1] : 0;
        ga1L[dd] = (n > 1) ? gam * g_aval[(size_t)w*DD + 1] : 0.f;
    }

    const float* xb = x   + (size_t)b * CPD;
    float*       ob = out + (size_t)b * CPD;

    // slab loader: li = channel pair, j0 = e block
    const int li = t >> 3;               // 0..31
    const int j0 = (t & 7) * 12;

    float4 r4[6];
    #define LDG1(P) {                                                           \
        const float* s0 = xb + (size_t)(2*li)   * PDSTRIDE + (size_t)(P) * DD + j0; \
        const float* s1 = xb + (size_t)(2*li+1) * PDSTRIDE + (size_t)(P) * DD + j0; \
        _Pragma("unroll")                                                       \
        for (int q = 0; q < 3; ++q) {                                           \
            r4[q]   = *reinterpret_cast<const float4*>(s0 + 4*q);               \
            r4[3+q] = *reinterpret_cast<const float4*>(s1 + 4*q); } }
    #define STS1(BUF) {                                                         \
        _Pragma("unroll")                                                       \
        for (int q = 0; q < 3; ++q) {                                           \
            *reinterpret_cast<float4*>(&(BUF)[(2*li)*SXS   + j0 + 4*q]) = r4[q]; \
            *reinterpret_cast<float4*>(&(BUF)[(2*li+1)*SXS + j0 + 4*q]) = r4[3+q]; } }

    LDG1(p0);
    STS1(sX0);
    __syncthreads();                     // X0 visible

    for (int pp = 0; pp < OPB; ++pp) {
        const int p = p0 + pp;
        const float* sX = sX0 + (pp & 1) * (CC*SXS);

        if (pp + 1 < OPB) LDG1(p + 1);

        // ---- y-gather + split-bf16 into B tiles ----
        #pragma unroll
        for (int dd = 0; dd < 3; ++dd) {
            const int d  = lane + 32*dd;
            const int e0 = e0L[dd], e1 = e1L[dd];
            const float a0 = ga0L[dd], a1 = ga1L[dd];
            #pragma unroll
            for (int w = 0; w < 4; ++w) {
                const int c2p = 4*wrp + w;
                const int c2  = 2*c2p;
                float ylo = fmaf(a0, sX[c2*SXS + e0],     a1 * sX[c2*SXS + e1]);
                float yhi = fmaf(a0, sX[(c2+1)*SXS + e0], a1 * sX[(c2+1)*SXS + e1]);
                if (nL[dd] > 2) {        // rare exact tail
                    const size_t wr = (size_t)(b*DD + d) * DD;
                    for (int k = 2; k < nL[dd]; ++k) {
                        const float ak = gam * g_aval[wr + k];
                        const int   ek = g_eidx[wr + k];
                        ylo = fmaf(ak, sX[c2*SXS + ek],     ylo);
                        yhi = fmaf(ak, sX[(c2+1)*SXS + ek], yhi);
                    }
                }
                __nv_bfloat16 h0, l0, h1, l1;
                splitbf(ylo, h0, l0);
                splitbf(yhi, h1, l1);
                sBh[d*XBW + c2p] = pkbf(h0, h1);
                sBl[d*XBW + c2p] = pkbf(l0, l1);
            }
        }
        __syncthreads();                 // (b) B tiles visible; sX read done

        if (pp + 1 < OPB) STS1(sX0 + ((pp + 1) & 1) * (CC*SXS));

        // ---- mma: D = Wv*y (split-3) + gamma*bv ----
        float dacc[6][4];
        #pragma unroll
        for (int nt = 0; nt < 6; ++nt) {
            dacc[nt][0] = gbA; dacc[nt][1] = gbA;
            dacc[nt][2] = gbB; dacc[nt][3] = gbB;
        }
        #pragma unroll
        for (int nt = 0; nt < 6; ++nt) {
            const int db = nb + nt*8 + lg;
            #pragma unroll
            for (int kt = 0; kt < 4; ++kt) {
                const int wof = db*XBW + kt*8 + tc;
                const u32 b0h = sBh[wof], b1h = sBh[wof + 4];
                const u32 b0l = sBl[wof], b1l = sBl[wof + 4];
                mma16816(dacc[nt], ah[kt], b0h, b1h);
                mma16816(dacc[nt], al[kt], b0h, b1h);
                mma16816(dacc[nt], ah[kt], b0l, b1l);
            }
        }

        // ---- epilogue: out = dacc + x residual, straight from fragments ----
        {
            const int r0 = mt*16 + lg, r1 = r0 + 8;
            float* o0 = ob + (size_t)r0 * PDSTRIDE + (size_t)p * DD;
            float* o1 = ob + (size_t)r1 * PDSTRIDE + (size_t)p * DD;
            #pragma unroll
            for (int nt = 0; nt < 6; ++nt) {
                const int ec = nb + nt*8 + 2*tc;
                const float2 xr0 = *reinterpret_cast<const float2*>(&sX[r0*SXS + ec]);
                const float2 xr1 = *reinterpret_cast<const float2*>(&sX[r1*SXS + ec]);
                float2 v0; v0.x = dacc[nt][0] + xr0.x; v0.y = dacc[nt][1] + xr0.y;
                float2 v1; v1.x = dacc[nt][2] + xr1.x; v1.y = dacc[nt][3] + xr1.y;
                *reinterpret_cast<float2*>(o0 + ec) = v0;
                *reinterpret_cast<float2*>(o1 + ec) = v1;
            }
        }
        __syncthreads();                 // (c) sB reusable; next sX visible
    }
    #undef LDG1
    #undef STS1
}

// ---------------------------------------------------------------------------
extern "C" void kernel_launch(void* const* d_in, const int* in_sizes, int n_in,
                              void* d_out, int out_size)
{
    const float* x  = (const float*)d_in[0];
    const float* Wq = (const float*)d_in[1];
    const float* bq = (const float*)d_in[2];
    const float* Wk = (const float*)d_in[3];
    const float* bk = (const float*)d_in[4];
    const float* Wv = (const float*)d_in[5];
    const float* bv = (const float*)d_in[6];
    const float* gm = (const float*)d_in[7];
    float* out = (float*)d_out;

    void* eptr = nullptr;
    cudaGetSymbolAddress(&eptr, g_energy);
    cudaMemsetAsync(eptr, 0, sizeof(double)*BB*DD*DD, 0);

    cudaFuncSetAttribute(energy_k, cudaFuncAttributeMaxDynamicSharedMemorySize,
                         E_FLOATS * (int)sizeof(float));
    energy_k<<<dim3(PP/PCHUNK, BB), 256, E_FLOATS*sizeof(float)>>>(x, Wq, bq, Wk, bk);

    softmax_k<<<(BB*DD*32 + 127)/128, 128>>>();

    cudaFuncSetAttribute(outy_k, cudaFuncAttributeMaxDynamicSharedMemorySize,
                         Y_FLOATS * (int)sizeof(float));
    outy_k<<<dim3(PP/OPB, BB), 256, Y_FLOATS*sizeof(float)>>>(x, Wv, bv, gm, out);
}